// round 1
// baseline (speedup 1.0000x reference)
#include <cuda_runtime.h>
#include <cstdint>

// out[i] = W[inputs[i] - 1]
// N = 16384 * 200 = 3,276,800 elements, W has 200 floats.
// Indices may arrive as int64 or int32 depending on jax x64 config;
// values are in [1, 200], so for int64 (little-endian) the 2nd 32-bit
// word of element 0 is 0, while for int32 element 1 is >= 1. We probe
// word[1] to pick the layout (deterministic, same every call).

#define N_TOTAL   (16384 * 200)
#define MAX_RANKS 200
#define TPB       256
#define VEC       4   // elements per thread

__global__ __launch_bounds__(TPB)
void bias_gather_kernel(const uint32_t* __restrict__ idx_raw,
                        const float* __restrict__ W,
                        float* __restrict__ out)
{
    __shared__ float sW[MAX_RANKS];
    int tid = threadIdx.x;
    if (tid < MAX_RANKS) sW[tid] = W[tid];

    // Probe dtype: word[1] == 0  => int64 indices (high word of elem 0)
    //              word[1] != 0  => int32 indices (elem 1, in [1,200])
    uint32_t probe = idx_raw[1];   // broadcast load, L1 hit for all threads
    __syncthreads();

    long long base = (long long)(blockIdx.x * TPB + tid) * VEC;
    if (base >= N_TOTAL) return;

    float4 r;
    if (probe == 0u) {
        // int64 layout: 4 indices = 32 bytes = two 16B loads
        const ulonglong2* p = reinterpret_cast<const ulonglong2*>(idx_raw) + (base >> 1);
        ulonglong2 a = p[0];
        ulonglong2 b = p[1];
        r.x = sW[(int)a.x - 1];
        r.y = sW[(int)a.y - 1];
        r.z = sW[(int)b.x - 1];
        r.w = sW[(int)b.y - 1];
    } else {
        // int32 layout: 4 indices = one 16B load
        const int4* p = reinterpret_cast<const int4*>(idx_raw) + (base >> 2);
        int4 a = p[0];
        r.x = sW[a.x - 1];
        r.y = sW[a.y - 1];
        r.z = sW[a.z - 1];
        r.w = sW[a.w - 1];
    }
    reinterpret_cast<float4*>(out)[base >> 2] = r;
}

extern "C" void kernel_launch(void* const* d_in, const int* in_sizes, int n_in,
                              void* d_out, int out_size)
{
    const uint32_t* idx = (const uint32_t*)d_in[0];  // inputs [16384, 200]
    const float*    W   = (const float*)d_in[1];     // [200, 1]
    float*          out = (float*)d_out;

    int threads_needed = N_TOTAL / VEC;              // 819,200
    int blocks = (threads_needed + TPB - 1) / TPB;   // 3200
    bias_gather_kernel<<<blocks, TPB>>>(idx, W, out);
}

// round 2
// speedup vs baseline: 1.0295x; 1.0295x over previous
#include <cuda_runtime.h>
#include <cstdint>

// out[i] = W[inputs[i] - 1];  N = 16384*200 = 3,276,800;  W: 200 floats.
// Indices may be int64 or int32 (probe word[1]: 0 => int64 high word).

#define N_TOTAL   (16384 * 200)
#define N_UNITS   (N_TOTAL / 4)      // float4 output units = 819,200
#define MAX_RANKS 200
#define TPB       512
#define NCTAS     (148 * 4)          // one full wave: 64 warps/SM

__global__ __launch_bounds__(TPB)
void bias_gather_kernel(const uint32_t* __restrict__ idx_raw,
                        const float* __restrict__ W,
                        float* __restrict__ out)
{
    // 32-way replicated W: sW[rank*32 + lane] -> bank == lane, conflict-free.
    __shared__ float sW[MAX_RANKS * 32];

    const int tid  = threadIdx.x;
    const int lane = tid & 31;
    const int wid  = tid >> 5;

    // Probe dtype early so the LDG overlaps with the smem fill below.
    uint32_t probe = idx_raw[1];

    // Warp-broadcast fill: each warp owns ranks {wid, wid+16, ...}
    #pragma unroll
    for (int k = wid; k < MAX_RANKS; k += TPB / 32) {
        float v = W[k];                 // same addr for all 32 lanes: 1 sector
        sW[k * 32 + lane] = v;          // conflict-free STS
    }
    __syncthreads();

    const long long g      = (long long)blockIdx.x * TPB + tid;
    const long long stride = (long long)gridDim.x * TPB;
    float4* __restrict__ out4 = reinterpret_cast<float4*>(out);

    if (probe == 0u) {
        // int64 indices: 4 idx = two 16B loads
        const ulonglong2* __restrict__ p = reinterpret_cast<const ulonglong2*>(idx_raw);
        for (long long u = g; u < N_UNITS; u += stride) {
            ulonglong2 a = p[2 * u];
            ulonglong2 b = p[2 * u + 1];
            float4 r;
            r.x = sW[((int)a.x - 1) * 32 + lane];
            r.y = sW[((int)a.y - 1) * 32 + lane];
            r.z = sW[((int)b.x - 1) * 32 + lane];
            r.w = sW[((int)b.y - 1) * 32 + lane];
            out4[u] = r;
        }
    } else {
        // int32 indices: 4 idx = one 16B load
        const int4* __restrict__ p = reinterpret_cast<const int4*>(idx_raw);
        for (long long u = g; u < N_UNITS; u += stride) {
            int4 a = p[u];
            float4 r;
            r.x = sW[(a.x - 1) * 32 + lane];
            r.y = sW[(a.y - 1) * 32 + lane];
            r.z = sW[(a.z - 1) * 32 + lane];
            r.w = sW[(a.w - 1) * 32 + lane];
            out4[u] = r;
        }
    }
}

extern "C" void kernel_launch(void* const* d_in, const int* in_sizes, int n_in,
                              void* d_out, int out_size)
{
    const uint32_t* idx = (const uint32_t*)d_in[0];  // inputs [16384, 200]
    const float*    W   = (const float*)d_in[1];     // [200, 1]
    float*          out = (float*)d_out;

    bias_gather_kernel<<<NCTAS, TPB>>>(idx, W, out);
}